// round 1
// baseline (speedup 1.0000x reference)
#include <cuda_runtime.h>

#define NV 50000
#define NE 400000
#define HVD 128
#define NOUT 256   // cols 0..127 -> mv path (Wa), 128..255 -> Y path (Wl_a + Wl_b)

// Scratch (device globals: no allocation allowed in kernel_launch)
__device__ float g_Y[(size_t)NV * HVD];   // per-vertex hv @ (Wl_a + Wl_b)
__device__ int   g_flag[NV];              // 1 if vertex appears in any edge endpoint
__device__ float g_W[HVD * NOUT];         // fused weight matrix [128, 256]

// ---------------------------------------------------------------------------
// Kernel 1: zero flags + build fused weight matrix  W = [Wa | Wl_a + Wl_b]
// ---------------------------------------------------------------------------
__global__ void prep_kernel(const float* __restrict__ Wa,
                            const float* __restrict__ Wl) {
    int idx = blockIdx.x * blockDim.x + threadIdx.x;
    int stride = gridDim.x * blockDim.x;
    for (int i = idx; i < NV; i += stride) g_flag[i] = 0;
    for (int i = idx; i < HVD * NOUT; i += stride) {
        int k = i / NOUT;
        int n = i % NOUT;
        float v;
        if (n < HVD) {
            v = Wa[k * HVD + n];                       // Wa: [128,128] row-major
        } else {
            int c = n - HVD;                           // Wl: [262,128] row-major
            v = Wl[k * 128 + c] + Wl[(134 + k) * 128 + c];
        }
        g_W[i] = v;
    }
}

// ---------------------------------------------------------------------------
// Kernel 2: mark vertices that appear as any endpoint (benign racing stores)
// ---------------------------------------------------------------------------
__global__ void flag_kernel(const int* __restrict__ eu, const int* __restrict__ ev) {
    int e = blockIdx.x * blockDim.x + threadIdx.x;
    if (e < NE) {
        g_flag[eu[e]] = 1;
        g_flag[ev[e]] = 1;
    }
}

// ---------------------------------------------------------------------------
// Kernel 3: fused vertex GEMM.  C[50000,256] = hv[50000,128] @ g_W[128,256]
//   cols 0..127  -> mv = flag ? elu(leaky_relu(x + ba)) : 0      -> d_out
//   cols 128..255-> Y  = x (bias added later in edge kernel)     -> g_Y
// Classic 128x128x8 tile, 8x8 per thread, 256 threads.
// ---------------------------------------------------------------------------
__global__ __launch_bounds__(256)
void gemm_kernel(const float* __restrict__ A,
                 const float* __restrict__ ba,
                 float* __restrict__ out_mv) {
    constexpr int BM = 128, BN = 128, BK = 8;
    __shared__ float As[BK][BM];
    __shared__ float Bs[BK][BN];

    const int row0 = blockIdx.x * BM;
    const int col0 = blockIdx.y * BN;
    const int t  = threadIdx.x;
    const int tx = t & 15;       // 0..15 (n)
    const int ty = t >> 4;       // 0..15 (m)

    // global-load mapping
    const int a_row = t >> 1;          // 0..127
    const int a_k4  = (t & 1) * 4;     // 0 or 4
    const int b_kr  = t >> 5;          // 0..7
    const int b_c4  = (t & 31) * 4;    // 0..124

    float acc[8][8];
#pragma unroll
    for (int i = 0; i < 8; i++)
#pragma unroll
        for (int j = 0; j < 8; j++) acc[i][j] = 0.f;

    for (int k0 = 0; k0 < HVD; k0 += BK) {
        // A tile 128x8 (transposed into As[k][m])
        float4 av = make_float4(0.f, 0.f, 0.f, 0.f);
        int gr = row0 + a_row;
        if (gr < NV)
            av = *reinterpret_cast<const float4*>(A + (size_t)gr * HVD + k0 + a_k4);
        As[a_k4 + 0][a_row] = av.x;
        As[a_k4 + 1][a_row] = av.y;
        As[a_k4 + 2][a_row] = av.z;
        As[a_k4 + 3][a_row] = av.w;
        // B tile 8x128
        *reinterpret_cast<float4*>(&Bs[b_kr][b_c4]) =
            *reinterpret_cast<const float4*>(g_W + (k0 + b_kr) * NOUT + col0 + b_c4);
        __syncthreads();

#pragma unroll
        for (int k = 0; k < BK; k++) {
            float4 a0 = *reinterpret_cast<float4*>(&As[k][ty * 8]);
            float4 a1 = *reinterpret_cast<float4*>(&As[k][ty * 8 + 4]);
            float4 b0 = *reinterpret_cast<float4*>(&Bs[k][tx * 8]);
            float4 b1 = *reinterpret_cast<float4*>(&Bs[k][tx * 8 + 4]);
            float ar[8] = {a0.x, a0.y, a0.z, a0.w, a1.x, a1.y, a1.z, a1.w};
            float br[8] = {b0.x, b0.y, b0.z, b0.w, b1.x, b1.y, b1.z, b1.w};
#pragma unroll
            for (int i = 0; i < 8; i++)
#pragma unroll
                for (int j = 0; j < 8; j++)
                    acc[i][j] = fmaf(ar[i], br[j], acc[i][j]);
        }
        __syncthreads();
    }

    // epilogue
#pragma unroll
    for (int i = 0; i < 8; i++) {
        int r = row0 + ty * 8 + i;
        if (r >= NV) continue;
        int fl = g_flag[r];
#pragma unroll
        for (int j = 0; j < 8; j++) {
            int c = col0 + tx * 8 + j;
            float x = acc[i][j];
            if (c < HVD) {
                float v = x + ba[c];
                float l = v > 0.f ? v : 0.01f * v;          // leaky_relu
                float e = l > 0.f ? l : expm1f(l);          // elu
                out_mv[(size_t)r * HVD + c] = fl ? e : 0.f;
            } else {
                g_Y[(size_t)r * HVD + (c - HVD)] = x;
            }
        }
    }
}

// ---------------------------------------------------------------------------
// Kernel 4: per-edge output. One warp per edge, float4 per lane (128 floats).
//   me[e] = leaky_relu(Y[u] + Y[v] + 2*bl)
// ---------------------------------------------------------------------------
__global__ __launch_bounds__(256)
void edge_kernel(const int* __restrict__ eu, const int* __restrict__ ev,
                 const float* __restrict__ bl, float* __restrict__ out_me) {
    int warp = (blockIdx.x * blockDim.x + threadIdx.x) >> 5;
    int lane = threadIdx.x & 31;
    if (warp >= NE) return;
    int u = __ldg(eu + warp);
    int v = __ldg(ev + warp);
    const float4 yu = *reinterpret_cast<const float4*>(g_Y + (size_t)u * HVD + lane * 4);
    const float4 yv = *reinterpret_cast<const float4*>(g_Y + (size_t)v * HVD + lane * 4);
    const float4 b  = *reinterpret_cast<const float4*>(bl + lane * 4);
    float4 o;
    o.x = yu.x + yv.x + 2.f * b.x;
    o.y = yu.y + yv.y + 2.f * b.y;
    o.z = yu.z + yv.z + 2.f * b.z;
    o.w = yu.w + yv.w + 2.f * b.w;
    o.x = o.x > 0.f ? o.x : 0.01f * o.x;
    o.y = o.y > 0.f ? o.y : 0.01f * o.y;
    o.z = o.z > 0.f ? o.z : 0.01f * o.z;
    o.w = o.w > 0.f ? o.w : 0.01f * o.w;
    *reinterpret_cast<float4*>(out_me + (size_t)warp * HVD + lane * 4) = o;
}

// ---------------------------------------------------------------------------
// Launch
// Inputs (metadata order): 0 hv_ftr, 1 he_ftr, 2 p_ftr, 3 q_ftr, 4 edge_u,
//   5 edge_v, 6 Wa, 7 ba, 8 Wal, 9 bal, 10 Wl, 11 bl
// Output: mv_ftr [50000,128] then me_ftr [400000,128], fp32, concatenated.
// ---------------------------------------------------------------------------
extern "C" void kernel_launch(void* const* d_in, const int* in_sizes, int n_in,
                              void* d_out, int out_size) {
    const float* hv = (const float*)d_in[0];
    const int*   eu = (const int*)d_in[4];
    const int*   ev = (const int*)d_in[5];
    const float* Wa = (const float*)d_in[6];
    const float* ba = (const float*)d_in[7];
    const float* Wl = (const float*)d_in[10];
    const float* bl = (const float*)d_in[11];
    float* out = (float*)d_out;

    prep_kernel<<<128, 256>>>(Wa, Wl);
    flag_kernel<<<(NE + 255) / 256, 256>>>(eu, ev);
    dim3 g((NV + 127) / 128, 2);
    gemm_kernel<<<g, 256>>>(hv, ba, out);
    edge_kernel<<<(NE * 32) / 256, 256>>>(eu, ev, bl, out + (size_t)NV * HVD);
}

// round 3
// speedup vs baseline: 1.4324x; 1.4324x over previous
#include <cuda_runtime.h>
#include <cuda_bf16.h>
#include <cstdint>

#define NV 50000
#define NE 400000
#define HVD 128
#define NOUT 256

// ---------------------------------------------------------------------------
// Device scratch
// ---------------------------------------------------------------------------
__device__ float g_Y[(size_t)NV * HVD];                 // hv @ (Wl_a + Wl_b)
__device__ int   g_flag[NV];
__device__ __align__(16) __nv_bfloat16 g_Bhi[HVD * NOUT];  // [k][n] row-major
__device__ __align__(16) __nv_bfloat16 g_Blo[HVD * NOUT];

// SMEM layout (bytes). Padded rows: A stride 136 bf16 (272B), B 264 bf16 (528B).
#define A_STRIDE 272
#define B_STRIDE 528
#define S_AHI 0
#define S_ALO 34816
#define S_BHI 69632
#define S_BLO 137216
#define S_TOTAL 204800

__device__ __forceinline__ uint32_t smem_u32(const void* p) {
    uint32_t a;
    asm("{ .reg .u64 t; cvta.to.shared.u64 t, %1; cvt.u32.u64 %0, t; }"
        : "=r"(a) : "l"(p));
    return a;
}
#define LDMX4(r0, r1, r2, r3, a)                                              \
    asm volatile("ldmatrix.sync.aligned.m8n8.x4.shared.b16 {%0,%1,%2,%3}, [%4];" \
                 : "=r"(r0), "=r"(r1), "=r"(r2), "=r"(r3) : "r"(a))
#define LDMX4T(r0, r1, r2, r3, a)                                             \
    asm volatile("ldmatrix.sync.aligned.m8n8.x4.trans.shared.b16 {%0,%1,%2,%3}, [%4];" \
                 : "=r"(r0), "=r"(r1), "=r"(r2), "=r"(r3) : "r"(a))
#define MMA16816(d, a0, a1, a2, a3, b0, b1)                                   \
    asm volatile("mma.sync.aligned.m16n8k16.row.col.f32.bf16.bf16.f32 "       \
                 "{%0,%1,%2,%3}, {%4,%5,%6,%7}, {%8,%9}, {%0,%1,%2,%3};"      \
                 : "+f"((d)[0]), "+f"((d)[1]), "+f"((d)[2]), "+f"((d)[3])     \
                 : "r"(a0), "r"(a1), "r"(a2), "r"(a3), "r"(b0), "r"(b1))

// ---------------------------------------------------------------------------
// Kernel 1: zero flags + build split-bf16 B images.
//   W_fused[k][n] = (n<128) ? Wa[k][n] : Wl[k][n-128] + Wl[134+k][n-128]
// ---------------------------------------------------------------------------
__global__ void prep_kernel(const float* __restrict__ Wa,
                            const float* __restrict__ Wl) {
    int idx = blockIdx.x * blockDim.x + threadIdx.x;
    int stride = gridDim.x * blockDim.x;
    for (int i = idx; i < NV; i += stride) g_flag[i] = 0;
    for (int i = idx; i < HVD * NOUT; i += stride) {
        int k = i >> 8;
        int n = i & 255;
        float v;
        if (n < HVD) v = Wa[k * HVD + n];
        else {
            int c = n - HVD;
            v = Wl[k * 128 + c] + Wl[(134 + k) * 128 + c];
        }
        __nv_bfloat16 hi = __float2bfloat16(v);
        __nv_bfloat16 lo = __float2bfloat16(v - __bfloat162float(hi));
        g_Bhi[i] = hi;
        g_Blo[i] = lo;
    }
}

// ---------------------------------------------------------------------------
// Kernel 2: mark vertices with incident edges
// ---------------------------------------------------------------------------
__global__ void flag_kernel(const int* __restrict__ eu, const int* __restrict__ ev) {
    int e = blockIdx.x * blockDim.x + threadIdx.x;
    if (e < NE) {
        g_flag[eu[e]] = 1;
        g_flag[ev[e]] = 1;
    }
}

// ---------------------------------------------------------------------------
// Kernel 3: split-bf16 HMMA GEMM. D[128,256] = A[128,128] @ W[128,256]
//   3 passes: Ah*Bh + Ah*Bl + Al*Bh (fp32 accumulate)
//   512 threads, warp grid 4(m) x 4(n), warp tile 32x64 (mma m16n8k16).
// ---------------------------------------------------------------------------
__global__ void __launch_bounds__(512, 1)
gemm_kernel(const float* __restrict__ A,
            const float* __restrict__ ba,
            float* __restrict__ out_mv) {
    extern __shared__ __align__(16) unsigned char smem[];
    const uint32_t sb = smem_u32(smem);
    const int tid = threadIdx.x;
    const int wid = tid >> 5;
    const int lane = tid & 31;
    const int warp_m = wid & 3;       // rows warp_m*32
    const int warp_n = wid >> 2;      // cols warp_n*64
    const int row0 = blockIdx.x * 128;

    // ---- load & convert A tile (128x128 fp32 -> bf16 hi/lo, padded rows) ----
    #pragma unroll
    for (int it = 0; it < 8; it++) {
        int idx = tid + it * 512;          // 0..4095 float4s
        int row = idx >> 5;
        int col = (idx & 31) * 4;
        float4 v = make_float4(0.f, 0.f, 0.f, 0.f);
        int gr = row0 + row;
        if (gr < NV)
            v = *reinterpret_cast<const float4*>(A + (size_t)gr * HVD + col);
        __nv_bfloat16 h0 = __float2bfloat16(v.x);
        __nv_bfloat16 h1 = __float2bfloat16(v.y);
        __nv_bfloat16 h2 = __float2bfloat16(v.z);
        __nv_bfloat16 h3 = __float2bfloat16(v.w);
        __nv_bfloat16 l0 = __float2bfloat16(v.x - __bfloat162float(h0));
        __nv_bfloat16 l1 = __float2bfloat16(v.y - __bfloat162float(h1));
        __nv_bfloat16 l2 = __float2bfloat16(v.z - __bfloat162float(h2));
        __nv_bfloat16 l3 = __float2bfloat16(v.w - __bfloat162float(h3));
        uint32_t off = (uint32_t)row * A_STRIDE + (uint32_t)col * 2;
        ushort4 ph, pl;
        ph.x = *(unsigned short*)&h0; ph.y = *(unsigned short*)&h1;
        ph.z = *(unsigned short*)&h2; ph.w = *(unsigned short*)&h3;
        pl.x = *(unsigned short*)&l0; pl.y = *(unsigned short*)&l1;
        pl.z = *(unsigned short*)&l2; pl.w = *(unsigned short*)&l3;
        *reinterpret_cast<ushort4*>(smem + S_AHI + off) = ph;
        *reinterpret_cast<ushort4*>(smem + S_ALO + off) = pl;
    }

    // ---- copy B images into padded SMEM (from L2-resident globals) ----
    {
        const uint2* sh = reinterpret_cast<const uint2*>(g_Bhi);
        const uint2* sl = reinterpret_cast<const uint2*>(g_Blo);
        #pragma unroll
        for (int it = 0; it < 16; it++) {
            int idx = tid + it * 512;      // 0..8191 8B-chunks (64 per row)
            int k = idx >> 6;
            int c = idx & 63;
            uint32_t off = (uint32_t)k * B_STRIDE + (uint32_t)c * 8;
            *reinterpret_cast<uint2*>(smem + S_BHI + off) = sh[idx];
            *reinterpret_cast<uint2*>(smem + S_BLO + off) = sl[idx];
        }
    }
    __syncthreads();

    // ---- 3-pass HMMA mainloop ----
    float acc[16][4];
    #pragma unroll
    for (int t = 0; t < 16; t++)
        #pragma unroll
        for (int j = 0; j < 4; j++) acc[t][j] = 0.f;

    const uint32_t aPass[3] = {S_AHI, S_AHI, S_ALO};
    const uint32_t bPass[3] = {S_BHI, S_BLO, S_BHI};

    for (int p = 0; p < 3; p++) {
        // ldmatrix lane-address bases
        uint32_t abase = sb + aPass[p]
                       + (uint32_t)(warp_m * 32 + (lane & 15)) * A_STRIDE
                       + (uint32_t)(lane >> 4) * 16;
        uint32_t bbase = sb + bPass[p]
                       + (uint32_t)(lane & 15) * B_STRIDE
                       + (uint32_t)(warp_n * 64 + (lane >> 4) * 8) * 2;
        #pragma unroll
        for (int k = 0; k < 8; k++) {
            uint32_t af[2][4], bf[4][4];
            #pragma unroll
            for (int mi = 0; mi < 2; mi++)
                LDMX4(af[mi][0], af[mi][1], af[mi][2], af[mi][3],
                      abase + (uint32_t)k * 32 + (uint32_t)mi * (16 * A_STRIDE));
            #pragma unroll
            for (int nb = 0; nb < 4; nb++)
                LDMX4T(bf[nb][0], bf[nb][1], bf[nb][2], bf[nb][3],
                       bbase + (uint32_t)k * (16 * B_STRIDE) + (uint32_t)nb * 32);
            #pragma unroll
            for (int mi = 0; mi < 2; mi++)
                #pragma unroll
                for (int ni = 0; ni < 8; ni++) {
                    int nb = ni >> 1;
                    int h = (ni & 1) * 2;
                    MMA16816(acc[mi * 8 + ni],
                             af[mi][0], af[mi][1], af[mi][2], af[mi][3],
                             bf[nb][h], bf[nb][h + 1]);
                }
        }
    }

    // ---- epilogue ----
    const int r_base = row0 + warp_m * 32 + (lane >> 2);
    #pragma unroll
    for (int mi = 0; mi < 2; mi++) {
        int r0r = r_base + mi * 16;        // rows r0r and r0r+8
        int fl0 = (r0r     < NV) ? g_flag[r0r]     : 0;
        int fl1 = (r0r + 8 < NV) ? g_flag[r0r + 8] : 0;
        #pragma unroll
        for (int ni = 0; ni < 8; ni++) {
            int c = warp_n * 64 + ni * 8 + (lane & 3) * 2;
            float* ac = acc[mi * 8 + ni];
            if (c < HVD) {
                float b0 = __ldg(ba + c), b1 = __ldg(ba + c + 1);
                #pragma unroll
                for (int h = 0; h < 2; h++) {  // h=0 row r0r, h=1 row r0r+8
                    int r = r0r + h * 8;
                    if (r >= NV) continue;
                    int fl = h ? fl1 : fl0;
                    float x0 = ac[h * 2 + 0] + b0;
                    float x1 = ac[h * 2 + 1] + b1;
                    float l0 = x0 > 0.f ? x0 : 0.01f * x0;
                    float l1 = x1 > 0.f ? x1 : 0.01f * x1;
                    float e0 = l0 > 0.f ? l0 : expm1f(l0);
                    float e1 = l1 > 0.f ? l1 : expm1f(l1);
                    e0 = fl ? e0 : 0.f;
                    e1 = fl ? e1 : 0.f;
                    asm volatile("st.global.cs.v2.f32 [%0], {%1,%2};"
                                 :: "l"(out_mv + (size_t)r * HVD + c),
                                    "f"(e0), "f"(e1) : "memory");
                }
            } else {
                int cy = c - HVD;
                #pragma unroll
                for (int h = 0; h < 2; h++) {
                    int r = r0r + h * 8;
                    if (r >= NV) continue;
                    float2 o = make_float2(ac[h * 2 + 0], ac[h * 2 + 1]);
                    *reinterpret_cast<float2*>(g_Y + (size_t)r * HVD + cy) = o;
                }
            }
        }
    }
}

// ---------------------------------------------------------------------------
// Kernel 4: per-edge output, 2 edges per warp.
//   me[e] = leaky_relu(Y[u] + Y[v] + 2*bl)   (streaming stores)
// ---------------------------------------------------------------------------
__global__ __launch_bounds__(256)
void edge_kernel(const int* __restrict__ eu, const int* __restrict__ ev,
                 const float* __restrict__ bl, float* __restrict__ out_me) {
    int warp = (blockIdx.x * blockDim.x + threadIdx.x) >> 5;
    int lane = threadIdx.x & 31;
    int e0 = warp * 2;
    if (e0 >= NE) return;
    int u0 = __ldg(eu + e0), v0 = __ldg(ev + e0);
    int u1 = __ldg(eu + e0 + 1), v1 = __ldg(ev + e0 + 1);
    const float4* Y = reinterpret_cast<const float4*>(g_Y);
    float4 a0 = __ldg(Y + (size_t)u0 * 32 + lane);
    float4 b0 = __ldg(Y + (size_t)v0 * 32 + lane);
    float4 a1 = __ldg(Y + (size_t)u1 * 32 + lane);
    float4 b1 = __ldg(Y + (size_t)v1 * 32 + lane);
    float4 bb = __ldg(reinterpret_cast<const float4*>(bl) + lane);
    bb.x *= 2.f; bb.y *= 2.f; bb.z *= 2.f; bb.w *= 2.f;

    float4 o0, o1;
    o0.x = a0.x + b0.x + bb.x; o0.y = a0.y + b0.y + bb.y;
    o0.z = a0.z + b0.z + bb.z; o0.w = a0.w + b0.w + bb.w;
    o1.x = a1.x + b1.x + bb.x; o1.y = a1.y + b1.y + bb.y;
    o1.z = a1.z + b1.z + bb.z; o1.w = a1.w + b1.w + bb.w;
    o0.x = o0.x > 0.f ? o0.x : 0.01f * o0.x;
    o0.y = o0.y > 0.f ? o0.y : 0.01f * o0.y;
    o0.z = o0.z > 0.f ? o0.z : 0.01f * o0.z;
    o0.w = o0.w > 0.f ? o0.w : 0.01f * o0.w;
    o1.x = o1.x > 0.f ? o1.x : 0.01f * o1.x;
    o1.y = o1.y > 0.f ? o1.y : 0.01f * o1.y;
    o1.z = o1.z > 0.f ? o1.z : 0.01f * o1.z;
    o1.w = o1.w > 0.f ? o1.w : 0.01f * o1.w;

    float* p0 = out_me + (size_t)e0 * HVD + lane * 4;
    float* p1 = p0 + HVD;
    asm volatile("st.global.cs.v4.f32 [%0], {%1,%2,%3,%4};"
                 :: "l"(p0), "f"(o0.x), "f"(o0.y), "f"(o0.z), "f"(o0.w) : "memory");
    asm volatile("st.global.cs.v4.f32 [%0], {%1,%2,%3,%4};"
                 :: "l"(p1), "f"(o1.x), "f"(o1.y), "f"(o1.z), "f"(o1.w) : "memory");
}

// ---------------------------------------------------------------------------
// Launch.  Inputs: 0 hv, 1 he, 2 p, 3 q, 4 eu, 5 ev, 6 Wa, 7 ba, 8 Wal,
//                  9 bal, 10 Wl, 11 bl.  Output: mv [50000,128] ++ me [400000,128].
// ---------------------------------------------------------------------------
extern "C" void kernel_launch(void* const* d_in, const int* in_sizes, int n_in,
                              void* d_out, int out_size) {
    const float* hv = (const float*)d_in[0];
    const int*   eu = (const int*)d_in[4];
    const int*   ev = (const int*)d_in[5];
    const float* Wa = (const float*)d_in[6];
    const float* ba = (const float*)d_in[7];
    const float* Wl = (const float*)d_in[10];
    const float* bl = (const float*)d_in[11];
    float* out = (float*)d_out;

    static bool attr_set = false;
    if (!attr_set) {
        cudaFuncSetAttribute(gemm_kernel,
                             cudaFuncAttributeMaxDynamicSharedMemorySize, S_TOTAL);
        attr_set = true;
    }

    prep_kernel<<<128, 256>>>(Wa, Wl);
    flag_kernel<<<(NE + 255) / 256, 256>>>(eu, ev);
    gemm_kernel<<<(NV + 127) / 128, 512, S_TOTAL>>>(hv, ba, out);
    edge_kernel<<<(NE / 2 * 32 + 255) / 256, 256>>>(eu, ev, bl,
                                                    out + (size_t)NV * HVD);
}

// round 4
// speedup vs baseline: 1.6413x; 1.1458x over previous
#include <cuda_runtime.h>
#include <cuda_bf16.h>
#include <cstdint>

#define NV 50000
#define NE 400000
#define HVD 128
#define NOUT 256

// ---------------------------------------------------------------------------
// Device scratch
// ---------------------------------------------------------------------------
__device__ float g_Y[(size_t)NV * HVD];                 // hv @ (Wl_a + Wl_b)
__device__ int   g_flag[NV];
__device__ __align__(16) __nv_bfloat16 g_Bhi[HVD * NOUT];  // [k][n] row-major
__device__ __align__(16) __nv_bfloat16 g_Blo[HVD * NOUT];

// SMEM layout (bytes). Padded rows: A stride 136 bf16 (272B), B 264 bf16 (528B).
#define A_STRIDE 272
#define B_STRIDE 528
#define S_AHI 0
#define S_ALO 34816
#define S_BHI 69632
#define S_BLO 137216
#define S_TOTAL 204800

__device__ __forceinline__ uint32_t smem_u32(const void* p) {
    uint32_t a;
    asm("{ .reg .u64 t; cvta.to.shared.u64 t, %1; cvt.u32.u64 %0, t; }"
        : "=r"(a) : "l"(p));
    return a;
}
#define LDMX4(r0, r1, r2, r3, a)                                              \
    asm volatile("ldmatrix.sync.aligned.m8n8.x4.shared.b16 {%0,%1,%2,%3}, [%4];" \
                 : "=r"(r0), "=r"(r1), "=r"(r2), "=r"(r3) : "r"(a))
#define LDMX4T(r0, r1, r2, r3, a)                                             \
    asm volatile("ldmatrix.sync.aligned.m8n8.x4.trans.shared.b16 {%0,%1,%2,%3}, [%4];" \
                 : "=r"(r0), "=r"(r1), "=r"(r2), "=r"(r3) : "r"(a))
#define MMA16816(d, a0, a1, a2, a3, b0, b1)                                   \
    asm volatile("mma.sync.aligned.m16n8k16.row.col.f32.bf16.bf16.f32 "       \
                 "{%0,%1,%2,%3}, {%4,%5,%6,%7}, {%8,%9}, {%0,%1,%2,%3};"      \
                 : "+f"((d)[0]), "+f"((d)[1]), "+f"((d)[2]), "+f"((d)[3])     \
                 : "r"(a0), "r"(a1), "r"(a2), "r"(a3), "r"(b0), "r"(b1))
#define CP_ASYNC16(dst, src)                                                  \
    asm volatile("cp.async.cg.shared.global [%0], [%1], 16;"                  \
                 :: "r"(dst), "l"(src) : "memory")
#define CP_COMMIT()  asm volatile("cp.async.commit_group;" ::: "memory")
#define CP_WAIT0()   asm volatile("cp.async.wait_group 0;" ::: "memory")

// ---------------------------------------------------------------------------
// Kernel 1: zero flags + build split-bf16 B images.
// ---------------------------------------------------------------------------
__global__ void prep_kernel(const float* __restrict__ Wa,
                            const float* __restrict__ Wl) {
    int idx = blockIdx.x * blockDim.x + threadIdx.x;
    int stride = gridDim.x * blockDim.x;
    for (int i = idx; i < NV; i += stride) g_flag[i] = 0;
    for (int i = idx; i < HVD * NOUT; i += stride) {
        int k = i >> 8;
        int n = i & 255;
        float v;
        if (n < HVD) v = Wa[k * HVD + n];
        else {
            int c = n - HVD;
            v = Wl[k * 128 + c] + Wl[(134 + k) * 128 + c];
        }
        __nv_bfloat16 hi = __float2bfloat16(v);
        __nv_bfloat16 lo = __float2bfloat16(v - __bfloat162float(hi));
        g_Bhi[i] = hi;
        g_Blo[i] = lo;
    }
}

// ---------------------------------------------------------------------------
// Kernel 2: mark vertices with incident edges
// ---------------------------------------------------------------------------
__global__ void flag_kernel(const int* __restrict__ eu, const int* __restrict__ ev) {
    int e = blockIdx.x * blockDim.x + threadIdx.x;
    if (e < NE) {
        g_flag[eu[e]] = 1;
        g_flag[ev[e]] = 1;
    }
}

// ---------------------------------------------------------------------------
// Kernel 3: split-bf16 HMMA GEMM. D[128,256] = A[128,128] @ W[128,256]
//   Fused pass (Ah·Bh + Ah·Bl), then pass (Al·Bh). fp32 accumulate.
//   512 threads, warp grid 4(m) x 4(n), warp tile 32x64 (mma m16n8k16).
// ---------------------------------------------------------------------------
__global__ void __launch_bounds__(512, 1)
gemm_kernel(const float* __restrict__ A,
            const float* __restrict__ ba,
            float* __restrict__ out_mv) {
    extern __shared__ __align__(16) unsigned char smem[];
    const uint32_t sb = smem_u32(smem);
    const int tid = threadIdx.x;
    const int wid = tid >> 5;
    const int lane = tid & 31;
    const int warp_m = wid & 3;       // rows warp_m*32
    const int warp_n = wid >> 2;      // cols warp_n*64
    const int row0 = blockIdx.x * 128;

    // ---- B images global->SMEM via cp.async (overlaps A load/convert) ----
    {
        const char* sh = reinterpret_cast<const char*>(g_Bhi);
        const char* sl = reinterpret_cast<const char*>(g_Blo);
        #pragma unroll
        for (int it = 0; it < 8; it++) {
            int idx = tid + it * 512;      // 0..4095 16B-chunks (32 per row)
            int k = idx >> 5;
            int c = idx & 31;
            uint32_t off = (uint32_t)k * B_STRIDE + (uint32_t)c * 16;
            CP_ASYNC16(sb + S_BHI + off, sh + idx * 16);
            CP_ASYNC16(sb + S_BLO + off, sl + idx * 16);
        }
        CP_COMMIT();
    }

    // ---- load & convert A tile (128x128 fp32 -> bf16 hi/lo, padded rows) ----
    #pragma unroll
    for (int it = 0; it < 8; it++) {
        int idx = tid + it * 512;          // 0..4095 float4s
        int row = idx >> 5;
        int col = (idx & 31) * 4;
        float4 v = make_float4(0.f, 0.f, 0.f, 0.f);
        int gr = row0 + row;
        if (gr < NV)
            v = *reinterpret_cast<const float4*>(A + (size_t)gr * HVD + col);
        __nv_bfloat16 h0 = __float2bfloat16(v.x);
        __nv_bfloat16 h1 = __float2bfloat16(v.y);
        __nv_bfloat16 h2 = __float2bfloat16(v.z);
        __nv_bfloat16 h3 = __float2bfloat16(v.w);
        __nv_bfloat16 l0 = __float2bfloat16(v.x - __bfloat162float(h0));
        __nv_bfloat16 l1 = __float2bfloat16(v.y - __bfloat162float(h1));
        __nv_bfloat16 l2 = __float2bfloat16(v.z - __bfloat162float(h2));
        __nv_bfloat16 l3 = __float2bfloat16(v.w - __bfloat162float(h3));
        uint32_t off = (uint32_t)row * A_STRIDE + (uint32_t)col * 2;
        ushort4 ph, pl;
        ph.x = *(unsigned short*)&h0; ph.y = *(unsigned short*)&h1;
        ph.z = *(unsigned short*)&h2; ph.w = *(unsigned short*)&h3;
        pl.x = *(unsigned short*)&l0; pl.y = *(unsigned short*)&l1;
        pl.z = *(unsigned short*)&l2; pl.w = *(unsigned short*)&l3;
        *reinterpret_cast<ushort4*>(smem + S_AHI + off) = ph;
        *reinterpret_cast<ushort4*>(smem + S_ALO + off) = pl;
    }
    CP_WAIT0();
    __syncthreads();

    // ---- HMMA mainloop ----
    float acc[16][4];
    #pragma unroll
    for (int t = 0; t < 16; t++)
        #pragma unroll
        for (int j = 0; j < 4; j++) acc[t][j] = 0.f;

    const uint32_t a_lane_off = (uint32_t)(warp_m * 32 + (lane & 15)) * A_STRIDE
                              + (uint32_t)(lane >> 4) * 16;
    const uint32_t b_lane_off = (uint32_t)(lane & 15) * B_STRIDE
                              + (uint32_t)(warp_n * 64 + (lane >> 4) * 8) * 2;
    const uint32_t aHi = sb + S_AHI + a_lane_off;
    const uint32_t aLo = sb + S_ALO + a_lane_off;
    const uint32_t bHi = sb + S_BHI + b_lane_off;
    const uint32_t bLo = sb + S_BLO + b_lane_off;

    // Fused pass: D += Ah*Bh + Ah*Bl   (Ah loaded once per k)
    #pragma unroll
    for (int k = 0; k < 8; k++) {
        uint32_t af[2][4], bh[4][4], blf[4][4];
        #pragma unroll
        for (int mi = 0; mi < 2; mi++)
            LDMX4(af[mi][0], af[mi][1], af[mi][2], af[mi][3],
                  aHi + (uint32_t)k * 32 + (uint32_t)mi * (16 * A_STRIDE));
        #pragma unroll
        for (int nb = 0; nb < 4; nb++)
            LDMX4T(bh[nb][0], bh[nb][1], bh[nb][2], bh[nb][3],
                   bHi + (uint32_t)k * (16 * B_STRIDE) + (uint32_t)nb * 32);
        #pragma unroll
        for (int nb = 0; nb < 4; nb++)
            LDMX4T(blf[nb][0], blf[nb][1], blf[nb][2], blf[nb][3],
                   bLo + (uint32_t)k * (16 * B_STRIDE) + (uint32_t)nb * 32);
        #pragma unroll
        for (int mi = 0; mi < 2; mi++)
            #pragma unroll
            for (int ni = 0; ni < 8; ni++) {
                int nb = ni >> 1;
                int h = (ni & 1) * 2;
                MMA16816(acc[mi * 8 + ni],
                         af[mi][0], af[mi][1], af[mi][2], af[mi][3],
                         bh[nb][h], bh[nb][h + 1]);
            }
        #pragma unroll
        for (int mi = 0; mi < 2; mi++)
            #pragma unroll
            for (int ni = 0; ni < 8; ni++) {
                int nb = ni >> 1;
                int h = (ni & 1) * 2;
                MMA16816(acc[mi * 8 + ni],
                         af[mi][0], af[mi][1], af[mi][2], af[mi][3],
                         blf[nb][h], blf[nb][h + 1]);
            }
    }
    // Pass: D += Al*Bh
    #pragma unroll
    for (int k = 0; k < 8; k++) {
        uint32_t af[2][4], bh[4][4];
        #pragma unroll
        for (int mi = 0; mi < 2; mi++)
            LDMX4(af[mi][0], af[mi][1], af[mi][2], af[mi][3],
                  aLo + (uint32_t)k * 32 + (uint32_t)mi * (16 * A_STRIDE));
        #pragma unroll
        for (int nb = 0; nb < 4; nb++)
            LDMX4T(bh[nb][0], bh[nb][1], bh[nb][2], bh[nb][3],
                   bHi + (uint32_t)k * (16 * B_STRIDE) + (uint32_t)nb * 32);
        #pragma unroll
        for (int mi = 0; mi < 2; mi++)
            #pragma unroll
            for (int ni = 0; ni < 8; ni++) {
                int nb = ni >> 1;
                int h = (ni & 1) * 2;
                MMA16816(acc[mi * 8 + ni],
                         af[mi][0], af[mi][1], af[mi][2], af[mi][3],
                         bh[nb][h], bh[nb][h + 1]);
            }
    }

    // ---- epilogue ----
    const int r_base = row0 + warp_m * 32 + (lane >> 2);
    #pragma unroll
    for (int mi = 0; mi < 2; mi++) {
        int r0r = r_base + mi * 16;        // rows r0r and r0r+8
        int fl0 = (r0r     < NV) ? g_flag[r0r]     : 0;
        int fl1 = (r0r + 8 < NV) ? g_flag[r0r + 8] : 0;
        #pragma unroll
        for (int ni = 0; ni < 8; ni++) {
            int c = warp_n * 64 + ni * 8 + (lane & 3) * 2;
            float* ac = acc[mi * 8 + ni];
            if (c < HVD) {
                float b0 = __ldg(ba + c), b1 = __ldg(ba + c + 1);
                #pragma unroll
                for (int h = 0; h < 2; h++) {
                    int r = r0r + h * 8;
                    if (r >= NV) continue;
                    int fl = h ? fl1 : fl0;
                    float x0 = ac[h * 2 + 0] + b0;
                    float x1 = ac[h * 2 + 1] + b1;
                    float l0 = x0 > 0.f ? x0 : 0.01f * x0;
                    float l1 = x1 > 0.f ? x1 : 0.01f * x1;
                    float e0 = l0 > 0.f ? l0 : expm1f(l0);
                    float e1 = l1 > 0.f ? l1 : expm1f(l1);
                    e0 = fl ? e0 : 0.f;
                    e1 = fl ? e1 : 0.f;
                    asm volatile("st.global.cs.v2.f32 [%0], {%1,%2};"
                                 :: "l"(out_mv + (size_t)r * HVD + c),
                                    "f"(e0), "f"(e1) : "memory");
                }
            } else {
                int cy = c - HVD;
                #pragma unroll
                for (int h = 0; h < 2; h++) {
                    int r = r0r + h * 8;
                    if (r >= NV) continue;
                    float2 o = make_float2(ac[h * 2 + 0], ac[h * 2 + 1]);
                    *reinterpret_cast<float2*>(g_Y + (size_t)r * HVD + cy) = o;
                }
            }
        }
    }
}

// ---------------------------------------------------------------------------
// Kernel 4: per-edge output, 4 edges per warp (8 gathers in flight).
//   me[e] = leaky_relu(Y[u] + Y[v] + 2*bl)   (streaming stores)
// ---------------------------------------------------------------------------
__global__ __launch_bounds__(256)
void edge_kernel(const int* __restrict__ eu, const int* __restrict__ ev,
                 const float* __restrict__ bl, float* __restrict__ out_me) {
    int warp = (blockIdx.x * blockDim.x + threadIdx.x) >> 5;
    int lane = threadIdx.x & 31;
    int e0 = warp * 4;
    if (e0 >= NE) return;
    const int4 us = *reinterpret_cast<const int4*>(eu + e0);
    const int4 vs = *reinterpret_cast<const int4*>(ev + e0);
    const float4* Y = reinterpret_cast<const float4*>(g_Y);

    float4 a0 = __ldg(Y + (size_t)us.x * 32 + lane);
    float4 b0 = __ldg(Y + (size_t)vs.x * 32 + lane);
    float4 a1 = __ldg(Y + (size_t)us.y * 32 + lane);
    float4 b1 = __ldg(Y + (size_t)vs.y * 32 + lane);
    float4 a2 = __ldg(Y + (size_t)us.z * 32 + lane);
    float4 b2 = __ldg(Y + (size_t)vs.z * 32 + lane);
    float4 a3 = __ldg(Y + (size_t)us.w * 32 + lane);
    float4 b3 = __ldg(Y + (size_t)vs.w * 32 + lane);
    float4 bb = __ldg(reinterpret_cast<const float4*>(bl) + lane);
    bb.x *= 2.f; bb.y *= 2.f; bb.z *= 2.f; bb.w *= 2.f;

    float* p = out_me + (size_t)e0 * HVD + lane * 4;
#define EDGE_OUT(av, bv, idx) do {                                            \
        float4 o;                                                             \
        o.x = av.x + bv.x + bb.x; o.y = av.y + bv.y + bb.y;                   \
        o.z = av.z + bv.z + bb.z; o.w = av.w + bv.w + bb.w;                   \
        o.x = o.x > 0.f ? o.x : 0.01f * o.x;                                  \
        o.y = o.y > 0.f ? o.y : 0.01f * o.y;                                  \
        o.z = o.z > 0.f ? o.z : 0.01f * o.z;                                  \
        o.w = o.w > 0.f ? o.w : 0.01f * o.w;                                  \
        asm volatile("st.global.cs.v4.f32 [%0], {%1,%2,%3,%4};"               \
                     :: "l"(p + (idx) * HVD), "f"(o.x), "f"(o.y),             \
                        "f"(o.z), "f"(o.w) : "memory");                       \
    } while (0)
    EDGE_OUT(a0, b0, 0);
    EDGE_OUT(a1, b1, 1);
    EDGE_OUT(a2, b2, 2);
    EDGE_OUT(a3, b3, 3);
#undef EDGE_OUT
}

// ---------------------------------------------------------------------------
// Launch.  Inputs: 0 hv, 1 he, 2 p, 3 q, 4 eu, 5 ev, 6 Wa, 7 ba, 8 Wal,
//                  9 bal, 10 Wl, 11 bl.  Output: mv [50000,128] ++ me [400000,128].
// ---------------------------------------------------------------------------
extern "C" void kernel_launch(void* const* d_in, const int* in_sizes, int n_in,
                              void* d_out, int out_size) {
    const float* hv = (const float*)d_in[0];
    const int*   eu = (const int*)d_in[4];
    const int*   ev = (const int*)d_in[5];
    const float* Wa = (const float*)d_in[6];
    const float* ba = (const float*)d_in[7];
    const float* Wl = (const float*)d_in[10];
    const float* bl = (const float*)d_in[11];
    float* out = (float*)d_out;

    static bool attr_set = false;
    if (!attr_set) {
        cudaFuncSetAttribute(gemm_kernel,
                             cudaFuncAttributeMaxDynamicSharedMemorySize, S_TOTAL);
        attr_set = true;
    }

    prep_kernel<<<128, 256>>>(Wa, Wl);
    flag_kernel<<<(NE + 255) / 256, 256>>>(eu, ev);
    gemm_kernel<<<(NV + 127) / 128, 512, S_TOTAL>>>(hv, ba, out);
    // 4 edges per warp
    edge_kernel<<<(NE / 4 * 32 + 255) / 256, 256>>>(eu, ev, bl,
                                                    out + (size_t)NV * HVD);
}

// round 5
// speedup vs baseline: 2.0052x; 1.2217x over previous
#include <cuda_runtime.h>
#include <cuda_bf16.h>
#include <cstdint>

#define NV 50000
#define NE 400000
#define HVD 128
#define NOUT 256

// ---------------------------------------------------------------------------
// Device scratch
// ---------------------------------------------------------------------------
__device__ float g_Y[(size_t)NV * HVD];                 // hv @ (Wl_a + Wl_b)
__device__ int   g_flag[NV];
__device__ __align__(16) __nv_bfloat16 g_Bhi[HVD * NOUT];  // [k][n] row-major
__device__ __align__(16) __nv_bfloat16 g_Blo[HVD * NOUT];

// SMEM layout (bytes). Padded rows: A stride 136 bf16 (272B), B 264 bf16 (528B).
#define A_STRIDE 272
#define B_STRIDE 528
#define S_AHI 0
#define S_ALO 34816
#define S_BHI 69632
#define S_BLO 137216
#define S_TOTAL 204800

__device__ __forceinline__ uint32_t smem_u32(const void* p) {
    uint32_t a;
    asm("{ .reg .u64 t; cvta.to.shared.u64 t, %1; cvt.u32.u64 %0, t; }"
        : "=r"(a) : "l"(p));
    return a;
}
#define LDMX4(r0, r1, r2, r3, a)                                              \
    asm volatile("ldmatrix.sync.aligned.m8n8.x4.shared.b16 {%0,%1,%2,%3}, [%4];" \
                 : "=r"(r0), "=r"(r1), "=r"(r2), "=r"(r3) : "r"(a))
#define LDMX4T(r0, r1, r2, r3, a)                                             \
    asm volatile("ldmatrix.sync.aligned.m8n8.x4.trans.shared.b16 {%0,%1,%2,%3}, [%4];" \
                 : "=r"(r0), "=r"(r1), "=r"(r2), "=r"(r3) : "r"(a))
#define MMA16816(d, a0, a1, a2, a3, b0, b1)                                   \
    asm volatile("mma.sync.aligned.m16n8k16.row.col.f32.bf16.bf16.f32 "       \
                 "{%0,%1,%2,%3}, {%4,%5,%6,%7}, {%8,%9}, {%0,%1,%2,%3};"      \
                 : "+f"((d)[0]), "+f"((d)[1]), "+f"((d)[2]), "+f"((d)[3])     \
                 : "r"(a0), "r"(a1), "r"(a2), "r"(a3), "r"(b0), "r"(b1))
#define CP_ASYNC16(dst, src)                                                  \
    asm volatile("cp.async.cg.shared.global [%0], [%1], 16;"                  \
                 :: "r"(dst), "l"(src) : "memory")
#define CP_COMMIT()  asm volatile("cp.async.commit_group;" ::: "memory")
#define CP_WAIT0()   asm volatile("cp.async.wait_group 0;" ::: "memory")

// ---------------------------------------------------------------------------
// Kernel 1: zero flags + build split-bf16 B images.
// ---------------------------------------------------------------------------
__global__ void prep_kernel(const float* __restrict__ Wa,
                            const float* __restrict__ Wl) {
    int idx = blockIdx.x * blockDim.x + threadIdx.x;
    int stride = gridDim.x * blockDim.x;
    for (int i = idx; i < NV; i += stride) g_flag[i] = 0;
    for (int i = idx; i < HVD * NOUT; i += stride) {
        int k = i >> 8;
        int n = i & 255;
        float v;
        if (n < HVD) v = Wa[k * HVD + n];
        else {
            int c = n - HVD;
            v = Wl[k * 128 + c] + Wl[(134 + k) * 128 + c];
        }
        __nv_bfloat16 hi = __float2bfloat16(v);
        __nv_bfloat16 lo = __float2bfloat16(v - __bfloat162float(hi));
        g_Bhi[i] = hi;
        g_Blo[i] = lo;
    }
}

// ---------------------------------------------------------------------------
// Kernel 2: mark vertices with incident edges
// ---------------------------------------------------------------------------
__global__ void flag_kernel(const int* __restrict__ eu, const int* __restrict__ ev) {
    int e = blockIdx.x * blockDim.x + threadIdx.x;
    if (e < NE) {
        g_flag[eu[e]] = 1;
        g_flag[ev[e]] = 1;
    }
}

// ---------------------------------------------------------------------------
// Kernel 3: split-bf16 HMMA GEMM, two N-half phases (low register pressure).
//   Phase 0: cols 0..127  -> mv (elu(leaky(x+ba)) masked by flag)
//   Phase 1: cols 128..255-> Y
//   Each phase: fused (Ah·Bh + Ah·Bl) then (Al·Bh).  fp32 accum.
//   512 threads, warp grid 4(m) x 4(n), warp tile 32x32 per phase.
// ---------------------------------------------------------------------------
__global__ void __launch_bounds__(512, 1)
gemm_kernel(const float* __restrict__ A,
            const float* __restrict__ ba,
            float* __restrict__ out_mv) {
    extern __shared__ __align__(16) unsigned char smem[];
    const uint32_t sb = smem_u32(smem);
    const int tid = threadIdx.x;
    const int wid = tid >> 5;
    const int lane = tid & 31;
    const int warp_m = wid & 3;       // rows warp_m*32
    const int warp_n = wid >> 2;      // cols warp_n*32 (within phase half)
    const int row0 = blockIdx.x * 128;

    // ---- B images global->SMEM via cp.async (overlaps A load/convert) ----
    {
        const char* sh = reinterpret_cast<const char*>(g_Bhi);
        const char* sl = reinterpret_cast<const char*>(g_Blo);
        #pragma unroll
        for (int it = 0; it < 8; it++) {
            int idx = tid + it * 512;      // 0..4095 16B-chunks (32 per row)
            int k = idx >> 5;
            int c = idx & 31;
            uint32_t off = (uint32_t)k * B_STRIDE + (uint32_t)c * 16;
            CP_ASYNC16(sb + S_BHI + off, sh + idx * 16);
            CP_ASYNC16(sb + S_BLO + off, sl + idx * 16);
        }
        CP_COMMIT();
    }

    // ---- load & convert A tile (128x128 fp32 -> bf16 hi/lo, padded rows) ----
    #pragma unroll
    for (int it = 0; it < 8; it++) {
        int idx = tid + it * 512;          // 0..4095 float4s
        int row = idx >> 5;
        int col = (idx & 31) * 4;
        float4 v = make_float4(0.f, 0.f, 0.f, 0.f);
        int gr = row0 + row;
        if (gr < NV)
            v = *reinterpret_cast<const float4*>(A + (size_t)gr * HVD + col);
        __nv_bfloat16 h0 = __float2bfloat16(v.x);
        __nv_bfloat16 h1 = __float2bfloat16(v.y);
        __nv_bfloat16 h2 = __float2bfloat16(v.z);
        __nv_bfloat16 h3 = __float2bfloat16(v.w);
        __nv_bfloat16 l0 = __float2bfloat16(v.x - __bfloat162float(h0));
        __nv_bfloat16 l1 = __float2bfloat16(v.y - __bfloat162float(h1));
        __nv_bfloat16 l2 = __float2bfloat16(v.z - __bfloat162float(h2));
        __nv_bfloat16 l3 = __float2bfloat16(v.w - __bfloat162float(h3));
        uint32_t off = (uint32_t)row * A_STRIDE + (uint32_t)col * 2;
        ushort4 ph, pl;
        ph.x = *(unsigned short*)&h0; ph.y = *(unsigned short*)&h1;
        ph.z = *(unsigned short*)&h2; ph.w = *(unsigned short*)&h3;
        pl.x = *(unsigned short*)&l0; pl.y = *(unsigned short*)&l1;
        pl.z = *(unsigned short*)&l2; pl.w = *(unsigned short*)&l3;
        *reinterpret_cast<ushort4*>(smem + S_AHI + off) = ph;
        *reinterpret_cast<ushort4*>(smem + S_ALO + off) = pl;
    }
    CP_WAIT0();
    __syncthreads();

    const uint32_t a_lane_off = (uint32_t)(warp_m * 32 + (lane & 15)) * A_STRIDE
                              + (uint32_t)(lane >> 4) * 16;
    const uint32_t aHi = sb + S_AHI + a_lane_off;
    const uint32_t aLo = sb + S_ALO + a_lane_off;
    const uint32_t b_lane_base = (uint32_t)(lane & 15) * B_STRIDE
                               + (uint32_t)(warp_n * 32 + (lane >> 4) * 8) * 2;

    const int r_base = row0 + warp_m * 32 + (lane >> 2);

    #pragma unroll
    for (int phase = 0; phase < 2; phase++) {
        const uint32_t bHi = sb + S_BHI + b_lane_base + (uint32_t)phase * 256;
        const uint32_t bLo = sb + S_BLO + b_lane_base + (uint32_t)phase * 256;

        float acc[8][4];
        #pragma unroll
        for (int t = 0; t < 8; t++)
            #pragma unroll
            for (int j = 0; j < 4; j++) acc[t][j] = 0.f;

        // Fused pass: D += Ah*Bh + Ah*Bl
        #pragma unroll
        for (int k = 0; k < 8; k++) {
            uint32_t af[2][4], bf[2][4];
            #pragma unroll
            for (int mi = 0; mi < 2; mi++)
                LDMX4(af[mi][0], af[mi][1], af[mi][2], af[mi][3],
                      aHi + (uint32_t)k * 32 + (uint32_t)mi * (16 * A_STRIDE));
            #pragma unroll
            for (int nb = 0; nb < 2; nb++)
                LDMX4T(bf[nb][0], bf[nb][1], bf[nb][2], bf[nb][3],
                       bHi + (uint32_t)k * (16 * B_STRIDE) + (uint32_t)nb * 32);
            #pragma unroll
            for (int mi = 0; mi < 2; mi++)
                #pragma unroll
                for (int ni = 0; ni < 4; ni++)
                    MMA16816(acc[mi * 4 + ni],
                             af[mi][0], af[mi][1], af[mi][2], af[mi][3],
                             bf[ni >> 1][(ni & 1) * 2], bf[ni >> 1][(ni & 1) * 2 + 1]);
            #pragma unroll
            for (int nb = 0; nb < 2; nb++)
                LDMX4T(bf[nb][0], bf[nb][1], bf[nb][2], bf[nb][3],
                       bLo + (uint32_t)k * (16 * B_STRIDE) + (uint32_t)nb * 32);
            #pragma unroll
            for (int mi = 0; mi < 2; mi++)
                #pragma unroll
                for (int ni = 0; ni < 4; ni++)
                    MMA16816(acc[mi * 4 + ni],
                             af[mi][0], af[mi][1], af[mi][2], af[mi][3],
                             bf[ni >> 1][(ni & 1) * 2], bf[ni >> 1][(ni & 1) * 2 + 1]);
        }
        // Pass: D += Al*Bh
        #pragma unroll
        for (int k = 0; k < 8; k++) {
            uint32_t af[2][4], bf[2][4];
            #pragma unroll
            for (int mi = 0; mi < 2; mi++)
                LDMX4(af[mi][0], af[mi][1], af[mi][2], af[mi][3],
                      aLo + (uint32_t)k * 32 + (uint32_t)mi * (16 * A_STRIDE));
            #pragma unroll
            for (int nb = 0; nb < 2; nb++)
                LDMX4T(bf[nb][0], bf[nb][1], bf[nb][2], bf[nb][3],
                       bHi + (uint32_t)k * (16 * B_STRIDE) + (uint32_t)nb * 32);
            #pragma unroll
            for (int mi = 0; mi < 2; mi++)
                #pragma unroll
                for (int ni = 0; ni < 4; ni++)
                    MMA16816(acc[mi * 4 + ni],
                             af[mi][0], af[mi][1], af[mi][2], af[mi][3],
                             bf[ni >> 1][(ni & 1) * 2], bf[ni >> 1][(ni & 1) * 2 + 1]);
        }

        // ---- epilogue ----
        if (phase == 0) {
            #pragma unroll
            for (int mi = 0; mi < 2; mi++) {
                int r0r = r_base + mi * 16;
                int fl0 = (r0r     < NV) ? g_flag[r0r]     : 0;
                int fl1 = (r0r + 8 < NV) ? g_flag[r0r + 8] : 0;
                #pragma unroll
                for (int ni = 0; ni < 4; ni++) {
                    int c = warp_n * 32 + ni * 8 + (lane & 3) * 2;
                    float* ac = acc[mi * 4 + ni];
                    float b0 = __ldg(ba + c), b1 = __ldg(ba + c + 1);
                    #pragma unroll
                    for (int h = 0; h < 2; h++) {
                        int r = r0r + h * 8;
                        if (r >= NV) continue;
                        int fl = h ? fl1 : fl0;
                        float x0 = ac[h * 2 + 0] + b0;
                        float x1 = ac[h * 2 + 1] + b1;
                        float l0 = x0 > 0.f ? x0 : 0.01f * x0;
                        float l1 = x1 > 0.f ? x1 : 0.01f * x1;
                        float e0 = l0 > 0.f ? l0 : expm1f(l0);
                        float e1 = l1 > 0.f ? l1 : expm1f(l1);
                        e0 = fl ? e0 : 0.f;
                        e1 = fl ? e1 : 0.f;
                        asm volatile("st.global.cs.v2.f32 [%0], {%1,%2};"
                                     :: "l"(out_mv + (size_t)r * HVD + c),
                                        "f"(e0), "f"(e1) : "memory");
                    }
                }
            }
        } else {
            #pragma unroll
            for (int mi = 0; mi < 2; mi++) {
                int r0r = r_base + mi * 16;
                #pragma unroll
                for (int ni = 0; ni < 4; ni++) {
                    int cy = warp_n * 32 + ni * 8 + (lane & 3) * 2;
                    float* ac = acc[mi * 4 + ni];
                    #pragma unroll
                    for (int h = 0; h < 2; h++) {
                        int r = r0r + h * 8;
                        if (r >= NV) continue;
                        float2 o = make_float2(ac[h * 2 + 0], ac[h * 2 + 1]);
                        *reinterpret_cast<float2*>(g_Y + (size_t)r * HVD + cy) = o;
                    }
                }
            }
        }
    }
}

// ---------------------------------------------------------------------------
// Kernel 4: per-edge output, 4 edges per warp.
//   me[e] = leaky_relu(Y[u] + Y[v] + 2*bl)   (streaming stores; write-bound)
// ---------------------------------------------------------------------------
__global__ __launch_bounds__(256)
void edge_kernel(const int* __restrict__ eu, const int* __restrict__ ev,
                 const float* __restrict__ bl, float* __restrict__ out_me) {
    int warp = (blockIdx.x * blockDim.x + threadIdx.x) >> 5;
    int lane = threadIdx.x & 31;
    int e0 = warp * 4;
    if (e0 >= NE) return;
    const int4 us = *reinterpret_cast<const int4*>(eu + e0);
    const int4 vs = *reinterpret_cast<const int4*>(ev + e0);
    const float4* Y = reinterpret_cast<const float4*>(g_Y);

    float4 a0 = __ldg(Y + (size_t)us.x * 32 + lane);
    float4 b0 = __ldg(Y + (size_t)vs.x * 32 + lane);
    float4 a1 = __ldg(Y + (size_t)us.y * 32 + lane);
    float4 b1 = __ldg(Y + (size_t)vs.y * 32 + lane);
    float4 a2 = __ldg(Y + (size_t)us.z * 32 + lane);
    float4 b2 = __ldg(Y + (size_t)vs.z * 32 + lane);
    float4 a3 = __ldg(Y + (size_t)us.w * 32 + lane);
    float4 b3 = __ldg(Y + (size_t)vs.w * 32 + lane);
    float4 bb = __ldg(reinterpret_cast<const float4*>(bl) + lane);
    bb.x *= 2.f; bb.y *= 2.f; bb.z *= 2.f; bb.w *= 2.f;

    float* p = out_me + (size_t)e0 * HVD + lane * 4;
#define EDGE_OUT(av, bv, idx) do {                                            \
        float4 o;                                                             \
        o.x = av.x + bv.x + bb.x; o.y = av.y + bv.y + bb.y;                   \
        o.z = av.z + bv.z + bb.z; o.w = av.w + bv.w + bb.w;                   \
        o.x = o.x > 0.f ? o.x : 0.01f * o.x;                                  \
        o.y = o.y > 0.f ? o.y : 0.01f * o.y;                                  \
        o.z = o.z > 0.f ? o.z : 0.01f * o.z;                                  \
        o.w = o.w > 0.f ? o.w : 0.01f * o.w;                                  \
        asm volatile("st.global.cs.v4.f32 [%0], {%1,%2,%3,%4};"               \
                     :: "l"(p + (idx) * HVD), "f"(o.x), "f"(o.y),             \
                        "f"(o.z), "f"(o.w) : "memory");                       \
    } while (0)
    EDGE_OUT(a0, b0, 0);
    EDGE_OUT(a1, b1, 1);
    EDGE_OUT(a2, b2, 2);
    EDGE_OUT(a3, b3, 3);
#undef EDGE_OUT
}

// ---------------------------------------------------------------------------
// Launch.  Inputs: 0 hv, 1 he, 2 p, 3 q, 4 eu, 5 ev, 6 Wa, 7 ba, 8 Wal,
//                  9 bal, 10 Wl, 11 bl.  Output: mv [50000,128] ++ me [400000,128].
// ---------------------------------------------------------------------------
extern "C" void kernel_launch(void* const* d_in, const int* in_sizes, int n_in,
                              void* d_out, int out_size) {
    const float* hv = (const float*)d_in[0];
    const int*   eu = (const int*)d_in[4];
    const int*   ev = (const int*)d_in[5];
    const float* Wa = (const float*)d_in[6];
    const float* ba = (const float*)d_in[7];
    const float* Wl = (const float*)d_in[10];
    const float* bl = (const float*)d_in[11];
    float* out = (float*)d_out;

    static bool attr_set = false;
    if (!attr_set) {
        cudaFuncSetAttribute(gemm_kernel,
                             cudaFuncAttributeMaxDynamicSharedMemorySize, S_TOTAL);
        attr_set = true;
    }

    prep_kernel<<<128, 256>>>(Wa, Wl);
    flag_kernel<<<(NE + 255) / 256, 256>>>(eu, ev);
    gemm_kernel<<<(NV + 127) / 128, 512, S_TOTAL>>>(hv, ba, out);
    edge_kernel<<<(NE / 4 * 32 + 255) / 256, 256>>>(eu, ev, bl,
                                                    out + (size_t)NV * HVD);
}

// round 6
// speedup vs baseline: 2.1939x; 1.0941x over previous
#include <cuda_runtime.h>
#include <cuda_fp16.h>
#include <cstdint>

#define NV 50000
#define NE 400000
#define HVD 128
#define NOUT 256

// ---------------------------------------------------------------------------
// Device scratch
// ---------------------------------------------------------------------------
__device__ float g_Y[(size_t)NV * HVD];                 // hv @ (Wl_a+Wl_b) + bl
__device__ int   g_flag[NV];
__device__ __align__(16) __half g_Bhi[HVD * NOUT];      // [k][n] row-major fp16
__device__ __align__(16) __half g_Blo[HVD * NOUT];

// SMEM layout (bytes). Padded rows: A stride 136 fp16 (272B), B 264 fp16 (528B).
#define A_STRIDE 272
#define B_STRIDE 528
#define S_AHI 0
#define S_BHI 34816
#define S_BLO 102400
#define S_TOTAL 169984

__device__ __forceinline__ uint32_t smem_u32(const void* p) {
    uint32_t a;
    asm("{ .reg .u64 t; cvta.to.shared.u64 t, %1; cvt.u32.u64 %0, t; }"
        : "=r"(a) : "l"(p));
    return a;
}
#define LDMX4(r0, r1, r2, r3, a)                                              \
    asm volatile("ldmatrix.sync.aligned.m8n8.x4.shared.b16 {%0,%1,%2,%3}, [%4];" \
                 : "=r"(r0), "=r"(r1), "=r"(r2), "=r"(r3) : "r"(a))
#define LDMX4T(r0, r1, r2, r3, a)                                             \
    asm volatile("ldmatrix.sync.aligned.m8n8.x4.trans.shared.b16 {%0,%1,%2,%3}, [%4];" \
                 : "=r"(r0), "=r"(r1), "=r"(r2), "=r"(r3) : "r"(a))
#define MMA16816(d, a0, a1, a2, a3, b0, b1)                                   \
    asm volatile("mma.sync.aligned.m16n8k16.row.col.f32.f16.f16.f32 "         \
                 "{%0,%1,%2,%3}, {%4,%5,%6,%7}, {%8,%9}, {%0,%1,%2,%3};"      \
                 : "+f"((d)[0]), "+f"((d)[1]), "+f"((d)[2]), "+f"((d)[3])     \
                 : "r"(a0), "r"(a1), "r"(a2), "r"(a3), "r"(b0), "r"(b1))
#define CP_ASYNC16(dst, src)                                                  \
    asm volatile("cp.async.cg.shared.global [%0], [%1], 16;"                  \
                 :: "r"(dst), "l"(src) : "memory")
#define CP_COMMIT()  asm volatile("cp.async.commit_group;" ::: "memory")
#define CP_WAIT0()   asm volatile("cp.async.wait_group 0;" ::: "memory")

// ---------------------------------------------------------------------------
// Kernel 1: zero flags + build split-fp16 B images.
//   W_fused[k][n] = (n<128) ? Wa[k][n] : Wl[k][n-128] + Wl[134+k][n-128]
// ---------------------------------------------------------------------------
__global__ void prep_kernel(const float* __restrict__ Wa,
                            const float* __restrict__ Wl) {
    int idx = blockIdx.x * blockDim.x + threadIdx.x;
    int stride = gridDim.x * blockDim.x;
    for (int i = idx; i < NV; i += stride) g_flag[i] = 0;
    for (int i = idx; i < HVD * NOUT; i += stride) {
        int k = i >> 8;
        int n = i & 255;
        float v;
        if (n < HVD) v = Wa[k * HVD + n];
        else {
            int c = n - HVD;
            v = Wl[k * 128 + c] + Wl[(134 + k) * 128 + c];
        }
        __half hi = __float2half_rn(v);
        __half lo = __float2half_rn(v - __half2float(hi));
        g_Bhi[i] = hi;
        g_Blo[i] = lo;
    }
}

// ---------------------------------------------------------------------------
// Kernel 2: mark vertices with incident edges
// ---------------------------------------------------------------------------
__global__ void flag_kernel(const int* __restrict__ eu, const int* __restrict__ ev) {
    int e = blockIdx.x * blockDim.x + threadIdx.x;
    if (e < NE) {
        g_flag[eu[e]] = 1;
        g_flag[ev[e]] = 1;
    }
}

// ---------------------------------------------------------------------------
// Kernel 3: 2-pass split-fp16 HMMA GEMM.  D = Ah·Bh + Ah·Bl  (fp32 accum)
//   Phase 0: cols 0..127  -> mv = flag ? elu(leaky(x+ba)) : 0
//   Phase 1: cols 128..255-> Y + bl   (bias folded in)
//   512 threads, warp grid 4(m) x 4(n), warp tile 32x32 per phase.
// ---------------------------------------------------------------------------
__global__ void __launch_bounds__(512, 1)
gemm_kernel(const float* __restrict__ A,
            const float* __restrict__ ba,
            const float* __restrict__ bl,
            float* __restrict__ out_mv) {
    extern __shared__ __align__(16) unsigned char smem[];
    const uint32_t sb = smem_u32(smem);
    const int tid = threadIdx.x;
    const int wid = tid >> 5;
    const int lane = tid & 31;
    const int warp_m = wid & 3;       // rows warp_m*32
    const int warp_n = wid >> 2;      // cols warp_n*32 (within phase half)
    const int row0 = blockIdx.x * 128;

    // ---- B images global->SMEM via cp.async (overlaps A load/convert) ----
    {
        const char* sh = reinterpret_cast<const char*>(g_Bhi);
        const char* sl = reinterpret_cast<const char*>(g_Blo);
        #pragma unroll
        for (int it = 0; it < 8; it++) {
            int idx = tid + it * 512;      // 0..4095 16B-chunks (32 per row)
            int k = idx >> 5;
            int c = idx & 31;
            uint32_t off = (uint32_t)k * B_STRIDE + (uint32_t)c * 16;
            CP_ASYNC16(sb + S_BHI + off, sh + idx * 16);
            CP_ASYNC16(sb + S_BLO + off, sl + idx * 16);
        }
        CP_COMMIT();
    }

    // ---- load & convert A tile (128x128 fp32 -> fp16 hi, padded rows) ----
    #pragma unroll
    for (int it = 0; it < 8; it++) {
        int idx = tid + it * 512;          // 0..4095 float4s
        int row = idx >> 5;
        int col = (idx & 31) * 4;
        float4 v = make_float4(0.f, 0.f, 0.f, 0.f);
        int gr = row0 + row;
        if (gr < NV)
            v = *reinterpret_cast<const float4*>(A + (size_t)gr * HVD + col);
        __half2 p0 = __floats2half2_rn(v.x, v.y);
        __half2 p1 = __floats2half2_rn(v.z, v.w);
        uint32_t off = (uint32_t)row * A_STRIDE + (uint32_t)col * 2;
        uint2 pk;
        pk.x = *reinterpret_cast<uint32_t*>(&p0);
        pk.y = *reinterpret_cast<uint32_t*>(&p1);
        *reinterpret_cast<uint2*>(smem + S_AHI + off) = pk;
    }
    CP_WAIT0();
    __syncthreads();

    const uint32_t aHi = sb + S_AHI
                       + (uint32_t)(warp_m * 32 + (lane & 15)) * A_STRIDE
                       + (uint32_t)(lane >> 4) * 16;
    const uint32_t b_lane_base = (uint32_t)(lane & 15) * B_STRIDE
                               + (uint32_t)(warp_n * 32 + (lane >> 4) * 8) * 2;

    const int r_base = row0 + warp_m * 32 + (lane >> 2);

    #pragma unroll
    for (int phase = 0; phase < 2; phase++) {
        const uint32_t bHi = sb + S_BHI + b_lane_base + (uint32_t)phase * 256;
        const uint32_t bLo = sb + S_BLO + b_lane_base + (uint32_t)phase * 256;

        float acc[8][4];
        #pragma unroll
        for (int t = 0; t < 8; t++)
            #pragma unroll
            for (int j = 0; j < 4; j++) acc[t][j] = 0.f;

        // Fused loop: D += Ah*Bh + Ah*Bl   (Ah fragments loaded once per k)
        #pragma unroll
        for (int k = 0; k < 8; k++) {
            uint32_t af[2][4], bf[2][4];
            #pragma unroll
            for (int mi = 0; mi < 2; mi++)
                LDMX4(af[mi][0], af[mi][1], af[mi][2], af[mi][3],
                      aHi + (uint32_t)k * 32 + (uint32_t)mi * (16 * A_STRIDE));
            #pragma unroll
            for (int nb = 0; nb < 2; nb++)
                LDMX4T(bf[nb][0], bf[nb][1], bf[nb][2], bf[nb][3],
                       bHi + (uint32_t)k * (16 * B_STRIDE) + (uint32_t)nb * 32);
            #pragma unroll
            for (int mi = 0; mi < 2; mi++)
                #pragma unroll
                for (int ni = 0; ni < 4; ni++)
                    MMA16816(acc[mi * 4 + ni],
                             af[mi][0], af[mi][1], af[mi][2], af[mi][3],
                             bf[ni >> 1][(ni & 1) * 2], bf[ni >> 1][(ni & 1) * 2 + 1]);
            #pragma unroll
            for (int nb = 0; nb < 2; nb++)
                LDMX4T(bf[nb][0], bf[nb][1], bf[nb][2], bf[nb][3],
                       bLo + (uint32_t)k * (16 * B_STRIDE) + (uint32_t)nb * 32);
            #pragma unroll
            for (int mi = 0; mi < 2; mi++)
                #pragma unroll
                for (int ni = 0; ni < 4; ni++)
                    MMA16816(acc[mi * 4 + ni],
                             af[mi][0], af[mi][1], af[mi][2], af[mi][3],
                             bf[ni >> 1][(ni & 1) * 2], bf[ni >> 1][(ni & 1) * 2 + 1]);
        }

        // ---- epilogue ----
        if (phase == 0) {
            #pragma unroll
            for (int mi = 0; mi < 2; mi++) {
                int r0r = r_base + mi * 16;
                int fl0 = (r0r     < NV) ? g_flag[r0r]     : 0;
                int fl1 = (r0r + 8 < NV) ? g_flag[r0r + 8] : 0;
                #pragma unroll
                for (int ni = 0; ni < 4; ni++) {
                    int c = warp_n * 32 + ni * 8 + (lane & 3) * 2;
                    float* ac = acc[mi * 4 + ni];
                    float b0 = __ldg(ba + c), b1 = __ldg(ba + c + 1);
                    #pragma unroll
                    for (int h = 0; h < 2; h++) {
                        int r = r0r + h * 8;
                        if (r >= NV) continue;
                        int fl = h ? fl1 : fl0;
                        float x0 = ac[h * 2 + 0] + b0;
                        float x1 = ac[h * 2 + 1] + b1;
                        float l0 = x0 > 0.f ? x0 : 0.01f * x0;
                        float l1 = x1 > 0.f ? x1 : 0.01f * x1;
                        float e0 = l0 > 0.f ? l0 : expm1f(l0);
                        float e1 = l1 > 0.f ? l1 : expm1f(l1);
                        e0 = fl ? e0 : 0.f;
                        e1 = fl ? e1 : 0.f;
                        asm volatile("st.global.cs.v2.f32 [%0], {%1,%2};"
                                     :: "l"(out_mv + (size_t)r * HVD + c),
                                        "f"(e0), "f"(e1) : "memory");
                    }
                }
            }
        } else {
            #pragma unroll
            for (int mi = 0; mi < 2; mi++) {
                int r0r = r_base + mi * 16;
                #pragma unroll
                for (int ni = 0; ni < 4; ni++) {
                    int cy = warp_n * 32 + ni * 8 + (lane & 3) * 2;
                    float* ac = acc[mi * 4 + ni];
                    float b0 = __ldg(bl + cy), b1 = __ldg(bl + cy + 1);
                    #pragma unroll
                    for (int h = 0; h < 2; h++) {
                        int r = r0r + h * 8;
                        if (r >= NV) continue;
                        float2 o = make_float2(ac[h * 2 + 0] + b0,
                                               ac[h * 2 + 1] + b1);
                        *reinterpret_cast<float2*>(g_Y + (size_t)r * HVD + cy) = o;
                    }
                }
            }
        }
    }
}

// ---------------------------------------------------------------------------
// Kernel 4: per-edge output, 4 edges per warp.
//   me[e] = leaky_relu(Yb[u] + Yb[v])   (bl pre-folded; streaming stores)
// ---------------------------------------------------------------------------
__global__ __launch_bounds__(256)
void edge_kernel(const int* __restrict__ eu, const int* __restrict__ ev,
                 float* __restrict__ out_me) {
    int warp = (blockIdx.x * blockDim.x + threadIdx.x) >> 5;
    int lane = threadIdx.x & 31;
    int e0 = warp * 4;
    if (e0 >= NE) return;
    const int4 us = *reinterpret_cast<const int4*>(eu + e0);
    const int4 vs = *reinterpret_cast<const int4*>(ev + e0);
    const float4* Y = reinterpret_cast<const float4*>(g_Y);

    float4 a0 = __ldg(Y + (size_t)us.x * 32 + lane);
    float4 b0 = __ldg(Y + (size_t)vs.x * 32 + lane);
    float4 a1 = __ldg(Y + (size_t)us.y * 32 + lane);
    float4 b1 = __ldg(Y + (size_t)vs.y * 32 + lane);
    float4 a2 = __ldg(Y + (size_t)us.z * 32 + lane);
    float4 b2 = __ldg(Y + (size_t)vs.z * 32 + lane);
    float4 a3 = __ldg(Y + (size_t)us.w * 32 + lane);
    float4 b3 = __ldg(Y + (size_t)vs.w * 32 + lane);

    float* p = out_me + (size_t)e0 * HVD + lane * 4;
#define EDGE_OUT(av, bv, idx) do {                                            \
        float4 o;                                                             \
        o.x = av.x + bv.x; o.y = av.y + bv.y;                                 \
        o.z = av.z + bv.z; o.w = av.w + bv.w;                                 \
        o.x = o.x > 0.f ? o.x : 0.01f * o.x;                                  \
        o.y = o.y > 0.f ? o.y : 0.01f * o.y;                                  \
        o.z = o.z > 0.f ? o.z : 0.01f * o.z;                                  \
        o.w = o.w > 0.f ? o.w : 0.01f * o.w;                                  \
        asm volatile("st.global.cs.v4.f32 [%0], {%1,%2,%3,%4};"               \
                     :: "l"(p + (idx) * HVD), "f"(o.x), "f"(o.y),             \
                        "f"(o.z), "f"(o.w) : "memory");                       \
    } while (0)
    EDGE_OUT(a0, b0, 0);
    EDGE_OUT(a1, b1, 1);
    EDGE_OUT(a2, b2, 2);
    EDGE_OUT(a3, b3, 3);
#undef EDGE_OUT
}

// ---------------------------------------------------------------------------
// Launch.  Inputs: 0 hv, 1 he, 2 p, 3 q, 4 eu, 5 ev, 6 Wa, 7 ba, 8 Wal,
//                  9 bal, 10 Wl, 11 bl.  Output: mv [50000,128] ++ me [400000,128].
// ---------------------------------------------------------------------------
extern "C" void kernel_launch(void* const* d_in, const int* in_sizes, int n_in,
                              void* d_out, int out_size) {
    const float* hv = (const float*)d_in[0];
    const int*   eu = (const int*)d_in[4];
    const int*   ev = (const int*)d_in[5];
    const float* Wa = (const float*)d_in[6];
    const float* ba = (const float*)d_in[7];
    const float* Wl = (const float*)d_in[10];
    const float* bl = (const float*)d_in[11];
    float* out = (float*)d_out;

    static bool attr_set = false;
    if (!attr_set) {
        cudaFuncSetAttribute(gemm_kernel,
                             cudaFuncAttributeMaxDynamicSharedMemorySize, S_TOTAL);
        attr_set = true;
    }

    prep_kernel<<<128, 256>>>(Wa, Wl);
    flag_kernel<<<(NE + 255) / 256, 256>>>(eu, ev);
    gemm_kernel<<<(NV + 127) / 128, 512, S_TOTAL>>>(hv, ba, bl, out);
    edge_kernel<<<(NE / 4 * 32 + 255) / 256, 256>>>(eu, ev,
                                                    out + (size_t)NV * HVD);
}